// round 2
// baseline (speedup 1.0000x reference)
#include <cuda_runtime.h>
#include <math.h>

// Shapes (all compile-time fixed)
//  T = 128 theta_in, NLON = 128, C = 64, L = 64, MF = 2L-1 = 127,
//  T_out = 128, K = 128 lon_out, COUT = 64.

#define PI_F 3.14159265358979323846f

// ---------------- scratch (device globals; no allocation) ----------------
__device__ float g_Fr[64*128*64];    // [m][t][c]   m = 0..63
__device__ float g_Fi[64*128*64];
__device__ float g_flmr[64*64*64];   // [l][m][c]   m = 0..63
__device__ float g_flmi[64*64*64];
__device__ float g_glr[64*127*64];   // [l][mf][o]  mf = 0..126
__device__ float g_gli[64*127*64];
__device__ float g_gr[128*127*64];   // [t][mf][o]
__device__ float g_gi[128*127*64];
__device__ float g_xs[128*128*64];   // [t][k][o]  x_spec
__device__ float g_cdft[64*128];     // cos(2*pi*m*n/128)
__device__ float g_sdft[64*128];
__device__ float g_cE[127*128];      // cos((mf-63)*2*pi*k/128)
__device__ float g_sE[127*128];
__device__ float g_tv[64];           // time_w @ w_t
__device__ float g_bt[64];           // b_t
__device__ float g_cw[64];           // sum_o conv_w[c,o]
__device__ float g_cb[1];            // sum_o conv_b[o]

// ---------------- twiddle tables (exact integer mod-128 reduction) -------
__global__ void k_tab() {
    int i = blockIdx.x * blockDim.x + threadIdx.x;
    const float w0 = 2.0f * PI_F / 128.0f;
    if (i < 64*128) {
        int m = i >> 7, n = i & 127;
        int r = (m * n) & 127;                  // period-128 exact reduction
        float s, c;
        sincosf(w0 * (float)r, &s, &c);
        g_cdft[i] = c;
        g_sdft[i] = s;
    } else if (i < 64*128 + 127*128) {
        int j = i - 64*128;
        int mf = j >> 7, k = j & 127;
        int m = mf - 63;
        int r = ((m * k) % 128 + 128) & 127;    // handles negative m
        float s, c;
        sincosf(w0 * (float)r, &s, &c);
        g_cE[mf*128 + k] = c;
        g_sE[mf*128 + k] = s;
    }
}

// ---------------- time-modulation precompute -----------------------------
// psi = t_emb @ dense_w; w_t = psi[:64], b_t = psi[64:]
// Reference einsum('ij,j,lmk->lmi') has 'k' as a FREE SUM:
//   h'[l,m,i] = (time_w @ w_t)[i] * (sum_k h[l,m,k]) + b_t[i]
// with h = x @ conv_w + conv_b, so
//   sum_k h = sum_c x[c]*cw_sum[c] + cb_sum.
__global__ void k_mod(const float* __restrict__ t_emb,
                      const float* __restrict__ dense_w,
                      const float* __restrict__ conv_w,
                      const float* __restrict__ conv_b,
                      const float* __restrict__ time_w) {
    __shared__ float psi[128];
    int tid = threadIdx.x;              // 128 threads
    float s = 0.f;
    for (int d = 0; d < 256; d++) s += t_emb[d] * dense_w[d*128 + tid];
    psi[tid] = s;
    __syncthreads();
    if (tid < 64) {
        float tv = 0.f;
        for (int j = 0; j < 64; j++) tv += time_w[tid*64 + j] * psi[j];
        g_tv[tid] = tv;
        g_bt[tid] = psi[64 + tid];
        float cs = 0.f;
        for (int o = 0; o < 64; o++) cs += conv_w[tid*64 + o];
        g_cw[tid] = cs;
    }
    if (tid == 64) {
        float cb = 0.f;
        for (int o = 0; o < 64; o++) cb += conv_b[o];
        g_cb[0] = cb;
    }
}

// ---------------- longitude DFT (m = 0..63 only; x real) -----------------
// Fr[m][t][c] =  (2pi/128)*qw[t] * sum_n x[t][n][c] cos(2pi m n/128)
// Fi[m][t][c] = -(2pi/128)*qw[t] * sum_n x[t][n][c] sin(2pi m n/128)
__global__ void k_dft(const float* __restrict__ x,
                      const float* __restrict__ quad_w) {
    int t = blockIdx.x;
    int tid = threadIdx.x;              // 256
    int c = tid & 63, q = tid >> 6;     // q = 0..3
    __shared__ float xs[128*64];
    const float* xrow = x + t*128*64;
    for (int i = tid; i < 128*64; i += 256) xs[i] = xrow[i];
    __syncthreads();
    float scale = (2.0f * PI_F / 128.0f) * quad_w[t];
    for (int m = q; m < 64; m += 4) {
        float ar = 0.f, ai = 0.f;
        const float* cd = g_cdft + m*128;
        const float* sd = g_sdft + m*128;
        #pragma unroll 4
        for (int n = 0; n < 128; n++) {
            float v = xs[n*64 + c];
            ar += v * cd[n];
            ai -= v * sd[n];
        }
        g_Fr[(m*128 + t)*64 + c] = ar * scale;
        g_Fi[(m*128 + t)*64 + c] = ai * scale;
    }
}

// ---------------- Legendre analysis: flm[l][m][c] = sum_t F[m][t][c]*P_in[l][63+m][t]
__global__ void k_ana(const float* __restrict__ P_in) {
    int m  = blockIdx.x;                // 0..63
    int l0 = blockIdx.y * 16;           // 4 l-tiles
    int c  = threadIdx.x;               // 64
    __shared__ float Ps[16][128];
    for (int i = c; i < 16*128; i += 64) {
        int li = i >> 7, tt = i & 127;
        Ps[li][tt] = P_in[((l0 + li)*127 + 63 + m)*128 + tt];
    }
    __syncthreads();
    float accr[16], acci[16];
    #pragma unroll
    for (int li = 0; li < 16; li++) { accr[li] = 0.f; acci[li] = 0.f; }
    for (int tt = 0; tt < 128; tt++) {
        float fr = g_Fr[(m*128 + tt)*64 + c];
        float fi = g_Fi[(m*128 + tt)*64 + c];
        #pragma unroll
        for (int li = 0; li < 16; li++) {
            float p = Ps[li][tt];
            accr[li] += fr * p;
            acci[li] += fi * p;
        }
    }
    for (int li = 0; li < 16; li++) {
        g_flmr[((l0 + li)*64 + m)*64 + c] = accr[li];
        g_flmi[((l0 + li)*64 + m)*64 + c] = acci[li];
    }
}

// ---------------- complex spectral weight multiply (HBM-bound: 266 MB) ---
// glm[l][mf][o] = sum_i flm[l][mf][i] * (wr + i*wi)[l][mf][i][o]
// flm at mf<63 derived: flm(l, 63-m) = (-1)^m conj(flm(l, 63+m))
__global__ void k_wmul(const float* __restrict__ wr,
                       const float* __restrict__ wi) {
    int mf = blockIdx.x, l = blockIdx.y;
    int o = threadIdx.x;                // 64
    __shared__ float ar[64], ai[64];
    {
        int i = o;
        float r, im;
        if (mf >= 63) {
            int m = mf - 63;
            r  = g_flmr[(l*64 + m)*64 + i];
            im = g_flmi[(l*64 + m)*64 + i];
        } else {
            int m = 63 - mf;
            float sgn = (m & 1) ? -1.f : 1.f;
            r  =  sgn * g_flmr[(l*64 + m)*64 + i];
            im = -sgn * g_flmi[(l*64 + m)*64 + i];
        }
        ar[i] = r; ai[i] = im;
    }
    __syncthreads();
    const float* wrp = wr + (size_t)(l*127 + mf)*4096 + o;
    const float* wip = wi + (size_t)(l*127 + mf)*4096 + o;
    float gr = 0.f, gi = 0.f;
    #pragma unroll 8
    for (int i = 0; i < 64; i++) {
        float wrv = wrp[i*64];
        float wiv = wip[i*64];
        gr += ar[i]*wrv - ai[i]*wiv;
        gi += ar[i]*wiv + ai[i]*wrv;
    }
    g_glr[(l*127 + mf)*64 + o] = gr;
    g_gli[(l*127 + mf)*64 + o] = gi;
}

// ---------------- Legendre synthesis: g[t][mf][o] = sum_l glm[l][mf][o]*P_out[l][mf][t]
__global__ void k_synl(const float* __restrict__ P_out) {
    int mf = blockIdx.x;
    int tid = threadIdx.x;              // 512
    int o = tid & 63, tq = tid >> 6;    // tq = 0..7, 16 t each
    __shared__ float Ps[64][128];       // [l][t]
    for (int i = tid; i < 64*128; i += 512) {
        int l = i >> 7, t2 = i & 127;
        Ps[l][t2] = P_out[(l*127 + mf)*128 + t2];
    }
    __syncthreads();
    float accr[16], acci[16];
    #pragma unroll
    for (int j = 0; j < 16; j++) { accr[j] = 0.f; acci[j] = 0.f; }
    for (int l = 0; l < 64; l++) {
        float gr = g_glr[(l*127 + mf)*64 + o];
        float gi = g_gli[(l*127 + mf)*64 + o];
        #pragma unroll
        for (int j = 0; j < 16; j++) {
            float p = Ps[l][tq*16 + j];
            accr[j] += gr * p;
            acci[j] += gi * p;
        }
    }
    for (int j = 0; j < 16; j++) {
        int t2 = tq*16 + j;
        g_gr[(t2*127 + mf)*64 + o] = accr[j];
        g_gi[(t2*127 + mf)*64 + o] = acci[j];
    }
}

// ---------------- inverse longitude transform ----------------------------
// x_spec[t][k][o] = sum_mf gr[t][mf][o]*cos((mf-63)phi_k) - gi*sin(...)
__global__ void k_ilon() {
    int t = blockIdx.x;
    int tid = threadIdx.x;              // 512
    int o = tid & 63, kq = tid >> 6;    // kq = 0..7, 16 k each
    __shared__ float grs[64*64], gis[64*64];
    float acc[16];
    #pragma unroll
    for (int j = 0; j < 16; j++) acc[j] = 0.f;
    for (int chunk = 0; chunk < 2; chunk++) {
        int mf0 = chunk * 64;
        int nmf = chunk ? 63 : 64;
        __syncthreads();
        for (int i = tid; i < nmf*64; i += 512) {
            grs[i] = g_gr[(t*127 + mf0)*64 + i];
            gis[i] = g_gi[(t*127 + mf0)*64 + i];
        }
        __syncthreads();
        for (int mm = 0; mm < nmf; mm++) {
            int mf = mf0 + mm;
            float gr = grs[mm*64 + o];
            float gi = gis[mm*64 + o];
            const float* cE = g_cE + mf*128 + kq*16;
            const float* sE = g_sE + mf*128 + kq*16;
            #pragma unroll
            for (int j = 0; j < 16; j++) {
                acc[j] += gr * cE[j];
                acc[j] -= gi * sE[j];
            }
        }
    }
    for (int j = 0; j < 16; j++)
        g_xs[(t*128 + kq*16 + j)*64 + o] = acc[j];
}

// ---------------- fused conv path + add + LayerNorm + ReLU ---------------
// v[t,k,o] = x_spec[t,k,o] + tv[o]*S(t,k) + b_t[o]
//   S(t,k) = sum_c x[t,k,c]*cw_sum[c] + cb_sum
// then LN over o + ReLU.
__global__ void k_final(const float* __restrict__ x,
                        const float* __restrict__ ln_scale,
                        const float* __restrict__ ln_bias,
                        float* __restrict__ out) {
    int t = blockIdx.x;
    int w = threadIdx.x >> 5, lane = threadIdx.x & 31; // 8 warps
    float cw1 = g_cw[lane],       cw2 = g_cw[lane + 32];
    float tv1 = g_tv[lane],       tv2 = g_tv[lane + 32];
    float bt1 = g_bt[lane],       bt2 = g_bt[lane + 32];
    float lns1 = ln_scale[lane],  lnb1 = ln_bias[lane];
    float lns2 = ln_scale[lane+32], lnb2 = ln_bias[lane+32];
    float cb = g_cb[0];
    for (int k = w; k < 128; k += 8) {
        const float* xp = x + (t*128 + k)*64;
        float x1 = xp[lane], x2 = xp[lane + 32];
        float S = x1*cw1 + x2*cw2;
        #pragma unroll
        for (int off = 16; off; off >>= 1)
            S += __shfl_xor_sync(0xffffffffu, S, off);
        S += cb;
        const float* xsp = g_xs + (t*128 + k)*64;
        float v1 = xsp[lane]      + tv1*S + bt1;
        float v2 = xsp[lane + 32] + tv2*S + bt2;
        float s  = v1 + v2;
        float sq = v1*v1 + v2*v2;
        #pragma unroll
        for (int off = 16; off; off >>= 1) {
            s  += __shfl_xor_sync(0xffffffffu, s,  off);
            sq += __shfl_xor_sync(0xffffffffu, sq, off);
        }
        float mu   = s * (1.0f/64.0f);
        float var  = sq * (1.0f/64.0f) - mu*mu;
        float rstd = rsqrtf(var + 1e-6f);
        float r1 = (v1 - mu)*rstd*lns1 + lnb1;
        float r2 = (v2 - mu)*rstd*lns2 + lnb2;
        float* op = out + (t*128 + k)*64;
        op[lane]      = fmaxf(r1, 0.f);
        op[lane + 32] = fmaxf(r2, 0.f);
    }
}

// ---------------- launch -------------------------------------------------
extern "C" void kernel_launch(void* const* d_in, const int* in_sizes, int n_in,
                              void* d_out, int out_size) {
    const float* x        = (const float*)d_in[0];
    const float* t_emb    = (const float*)d_in[1];
    const float* wr       = (const float*)d_in[2];
    const float* wi       = (const float*)d_in[3];
    const float* conv_w   = (const float*)d_in[4];
    const float* conv_b   = (const float*)d_in[5];
    const float* time_w   = (const float*)d_in[6];
    const float* dense_w  = (const float*)d_in[7];
    const float* ln_scale = (const float*)d_in[8];
    const float* ln_bias  = (const float*)d_in[9];
    const float* P_in     = (const float*)d_in[10];
    const float* P_out    = (const float*)d_in[11];
    const float* quad_w   = (const float*)d_in[12];
    float* out = (float*)d_out;

    k_tab  <<<96, 256>>>();
    k_mod  <<<1, 128>>>(t_emb, dense_w, conv_w, conv_b, time_w);
    k_dft  <<<128, 256>>>(x, quad_w);
    k_ana  <<<dim3(64, 4), 64>>>(P_in);
    k_wmul <<<dim3(127, 64), 64>>>(wr, wi);
    k_synl <<<127, 512>>>(P_out);
    k_ilon <<<128, 512>>>();
    k_final<<<128, 256>>>(x, ln_scale, ln_bias, out);
}

// round 3
// speedup vs baseline: 1.6973x; 1.6973x over previous
#include <cuda_runtime.h>
#include <math.h>

#define PI_F 3.14159265358979323846f

// ---------------- scratch (device globals; no allocation) ----------------
__device__ float g_Fr[64*128*64];    // [m][t][c]
__device__ float g_Fi[64*128*64];
__device__ float g_flmr[64*64*64];   // [l][m][c]
__device__ float g_flmi[64*64*64];
__device__ float g_glr[64*127*64];   // [l][mf][o]
__device__ float g_gli[64*127*64];
__device__ float g_gr[128*127*64];   // [t][mf][o]
__device__ float g_gi[128*127*64];
__device__ float g_xs[128*128*64];   // [t][k][o]
__device__ float g_cdft[64*128];
__device__ float g_sdft[64*128];
__device__ float g_cE[127*128];
__device__ float g_sE[127*128];
__device__ float g_tv[64];
__device__ float g_bt[64];
__device__ float g_cw[64];
__device__ float g_cb[1];

// ---------------- twiddle tables (exact integer mod-128 reduction) -------
__global__ void k_tab() {
    int i = blockIdx.x * blockDim.x + threadIdx.x;
    const float w0 = 2.0f * PI_F / 128.0f;
    if (i < 64*128) {
        int m = i >> 7, n = i & 127;
        int r = (m * n) & 127;
        float s, c;
        sincosf(w0 * (float)r, &s, &c);
        g_cdft[i] = c;
        g_sdft[i] = s;
    } else if (i < 64*128 + 127*128) {
        int j = i - 64*128;
        int mf = j >> 7, k = j & 127;
        int m = mf - 63;
        int r = ((m * k) % 128 + 128) & 127;
        float s, c;
        sincosf(w0 * (float)r, &s, &c);
        g_cE[mf*128 + k] = c;
        g_sE[mf*128 + k] = s;
    }
}

// ---------------- time-modulation precompute -----------------------------
__global__ void k_mod(const float* __restrict__ t_emb,
                      const float* __restrict__ dense_w,
                      const float* __restrict__ conv_w,
                      const float* __restrict__ conv_b,
                      const float* __restrict__ time_w) {
    __shared__ float psi[128];
    int tid = threadIdx.x;              // 128
    float s = 0.f;
    for (int d = 0; d < 256; d++) s += t_emb[d] * dense_w[d*128 + tid];
    psi[tid] = s;
    __syncthreads();
    if (tid < 64) {
        float tv = 0.f;
        for (int j = 0; j < 64; j++) tv += time_w[tid*64 + j] * psi[j];
        g_tv[tid] = tv;
        g_bt[tid] = psi[64 + tid];
        float cs = 0.f;
        for (int o = 0; o < 64; o++) cs += conv_w[tid*64 + o];
        g_cw[tid] = cs;
    }
    if (tid == 64) {
        float cb = 0.f;
        for (int o = 0; o < 64; o++) cb += conv_b[o];
        g_cb[0] = cb;
    }
}

// ---------------- longitude DFT: grid(t=128, mq=4), 512 threads ----------
// Each block: 16 m. 8 q-groups x 2 m per thread. Twiddles staged in smem.
__global__ void k_dft(const float* __restrict__ x,
                      const float* __restrict__ quad_w) {
    int t  = blockIdx.x;
    int m0 = blockIdx.y * 16;
    int tid = threadIdx.x;              // 512
    int c = tid & 63, q = tid >> 6;     // q = 0..7
    __shared__ float tc[16*128], ts[16*128];
    for (int i = tid; i < 16*128; i += 512) {
        tc[i] = g_cdft[m0*128 + i];
        ts[i] = g_sdft[m0*128 + i];
    }
    __syncthreads();
    const float* xrow = x + t*128*64 + c;
    float a0r = 0.f, a0i = 0.f, a1r = 0.f, a1i = 0.f;
    int mm0 = (q*2)*128, mm1 = (q*2 + 1)*128;
    #pragma unroll 4
    for (int n = 0; n < 128; n += 4) {
        float v0 = xrow[(n+0)*64];
        float v1 = xrow[(n+1)*64];
        float v2 = xrow[(n+2)*64];
        float v3 = xrow[(n+3)*64];
        float4 c0 = *(const float4*)&tc[mm0 + n];
        float4 s0 = *(const float4*)&ts[mm0 + n];
        float4 c1 = *(const float4*)&tc[mm1 + n];
        float4 s1 = *(const float4*)&ts[mm1 + n];
        a0r += v0*c0.x + v1*c0.y + v2*c0.z + v3*c0.w;
        a0i -= v0*s0.x + v1*s0.y + v2*s0.z + v3*s0.w;
        a1r += v0*c1.x + v1*c1.y + v2*c1.z + v3*c1.w;
        a1i -= v0*s1.x + v1*s1.y + v2*s1.z + v3*s1.w;
    }
    float scale = (2.0f * PI_F / 128.0f) * quad_w[t];
    int m = m0 + q*2;
    g_Fr[(m*128 + t)*64 + c]       = a0r * scale;
    g_Fi[(m*128 + t)*64 + c]       = a0i * scale;
    g_Fr[((m+1)*128 + t)*64 + c]   = a1r * scale;
    g_Fi[((m+1)*128 + t)*64 + c]   = a1i * scale;
}

// ---------------- Legendre analysis: grid(m=64, lt=4), 256 threads -------
// flm[l][m][c] = sum_t F[m][t][c] * P_in[l][63+m][t]; 4 l per thread.
__global__ void k_ana(const float* __restrict__ P_in) {
    int m  = blockIdx.x;
    int l0 = blockIdx.y * 16;
    int tid = threadIdx.x;              // 256
    int c = tid & 63, lq = tid >> 6;    // 4 groups x 4 l
    __shared__ float Ps[16][128];
    for (int i = tid; i < 16*128; i += 256)
        Ps[i >> 7][i & 127] = P_in[((l0 + (i >> 7))*127 + 63 + m)*128 + (i & 127)];
    __syncthreads();
    float accr[4] = {0,0,0,0}, acci[4] = {0,0,0,0};
    const float* Fr = g_Fr + m*128*64 + c;
    const float* Fi = g_Fi + m*128*64 + c;
    #pragma unroll 4
    for (int tt = 0; tt < 128; tt += 2) {
        float fr0 = Fr[tt*64],      fi0 = Fi[tt*64];
        float fr1 = Fr[tt*64 + 64], fi1 = Fi[tt*64 + 64];
        #pragma unroll
        for (int li = 0; li < 4; li++) {
            float p0 = Ps[lq*4 + li][tt];
            float p1 = Ps[lq*4 + li][tt + 1];
            accr[li] += fr0*p0 + fr1*p1;
            acci[li] += fi0*p0 + fi1*p1;
        }
    }
    #pragma unroll
    for (int li = 0; li < 4; li++) {
        int l = l0 + lq*4 + li;
        g_flmr[(l*64 + m)*64 + c] = accr[li];
        g_flmi[(l*64 + m)*64 + c] = acci[li];
    }
}

// ---------------- complex spectral weight multiply (266 MB stream) -------
// 256 threads: og=o/4 float4 (16), ig=i-range (16 x 4i). MLP=8 float4 loads.
__global__ void k_wmul(const float* __restrict__ wr,
                       const float* __restrict__ wi) {
    int mf = blockIdx.x, l = blockIdx.y;
    int tid = threadIdx.x;              // 256
    int og = tid & 15;
    int ig = tid >> 4;
    __shared__ float ar[64], ai[64];
    __shared__ float redr[16][64], redi[16][64];
    if (tid < 64) {
        int i = tid;
        float r, im;
        if (mf >= 63) {
            int m = mf - 63;
            r  = g_flmr[(l*64 + m)*64 + i];
            im = g_flmi[(l*64 + m)*64 + i];
        } else {
            int m = 63 - mf;
            float sgn = (m & 1) ? -1.f : 1.f;
            r  =  sgn * g_flmr[(l*64 + m)*64 + i];
            im = -sgn * g_flmi[(l*64 + m)*64 + i];
        }
        ar[i] = r; ai[i] = im;
    }
    __syncthreads();
    const float4* wr4 = (const float4*)(wr + (size_t)(l*127 + mf)*4096);
    const float4* wi4 = (const float4*)(wi + (size_t)(l*127 + mf)*4096);
    float4 gr = {0,0,0,0}, gi = {0,0,0,0};
    #pragma unroll
    for (int ii = 0; ii < 4; ii++) {
        int i = ig*4 + ii;
        float4 wrv = wr4[i*16 + og];
        float4 wiv = wi4[i*16 + og];
        float xr = ar[i], xi = ai[i];
        gr.x += xr*wrv.x - xi*wiv.x;  gi.x += xr*wiv.x + xi*wrv.x;
        gr.y += xr*wrv.y - xi*wiv.y;  gi.y += xr*wiv.y + xi*wrv.y;
        gr.z += xr*wrv.z - xi*wiv.z;  gi.z += xr*wiv.z + xi*wrv.z;
        gr.w += xr*wrv.w - xi*wiv.w;  gi.w += xr*wiv.w + xi*wrv.w;
    }
    *(float4*)&redr[ig][og*4] = gr;
    *(float4*)&redi[ig][og*4] = gi;
    __syncthreads();
    if (tid < 64) {
        float sr = 0.f, si = 0.f;
        #pragma unroll
        for (int g = 0; g < 16; g++) { sr += redr[g][tid]; si += redi[g][tid]; }
        g_glr[(l*127 + mf)*64 + tid] = sr;
        g_gli[(l*127 + mf)*64 + tid] = si;
    }
}

// ---------------- Legendre synthesis -------------------------------------
__global__ void k_synl(const float* __restrict__ P_out) {
    int mf = blockIdx.x;
    int tid = threadIdx.x;              // 512
    int o = tid & 63, tq = tid >> 6;    // 8 groups x 16 t
    __shared__ float Ps[64][128];
    for (int i = tid; i < 64*128; i += 512)
        Ps[i >> 7][i & 127] = P_out[((i >> 7)*127 + mf)*128 + (i & 127)];
    __syncthreads();
    float accr[16], acci[16];
    #pragma unroll
    for (int j = 0; j < 16; j++) { accr[j] = 0.f; acci[j] = 0.f; }
    const float* glr = g_glr + (size_t)0*64 + mf*64 + o;
    const float* gli = g_gli + mf*64 + o;
    #pragma unroll 2
    for (int l = 0; l < 64; l++) {
        float gr = glr[l*127*64];
        float gi = gli[l*127*64];
        float4 p0 = *(const float4*)&Ps[l][tq*16 + 0];
        float4 p1 = *(const float4*)&Ps[l][tq*16 + 4];
        float4 p2 = *(const float4*)&Ps[l][tq*16 + 8];
        float4 p3 = *(const float4*)&Ps[l][tq*16 + 12];
        accr[0]  += gr*p0.x; acci[0]  += gi*p0.x;
        accr[1]  += gr*p0.y; acci[1]  += gi*p0.y;
        accr[2]  += gr*p0.z; acci[2]  += gi*p0.z;
        accr[3]  += gr*p0.w; acci[3]  += gi*p0.w;
        accr[4]  += gr*p1.x; acci[4]  += gi*p1.x;
        accr[5]  += gr*p1.y; acci[5]  += gi*p1.y;
        accr[6]  += gr*p1.z; acci[6]  += gi*p1.z;
        accr[7]  += gr*p1.w; acci[7]  += gi*p1.w;
        accr[8]  += gr*p2.x; acci[8]  += gi*p2.x;
        accr[9]  += gr*p2.y; acci[9]  += gi*p2.y;
        accr[10] += gr*p2.z; acci[10] += gi*p2.z;
        accr[11] += gr*p2.w; acci[11] += gi*p2.w;
        accr[12] += gr*p3.x; acci[12] += gi*p3.x;
        accr[13] += gr*p3.y; acci[13] += gi*p3.y;
        accr[14] += gr*p3.z; acci[14] += gi*p3.z;
        accr[15] += gr*p3.w; acci[15] += gi*p3.w;
    }
    #pragma unroll
    for (int j = 0; j < 16; j++) {
        int t2 = tq*16 + j;
        g_gr[(t2*127 + mf)*64 + o] = accr[j];
        g_gi[(t2*127 + mf)*64 + o] = acci[j];
    }
}

// ---------------- inverse longitude transform ----------------------------
__global__ void k_ilon() {
    int t = blockIdx.x;
    int tid = threadIdx.x;              // 512
    int o = tid & 63, kq = tid >> 6;    // 8 groups x 16 k
    __shared__ float grs[16*64], gis[16*64];
    __shared__ float cEs[16*128], sEs[16*128];
    float acc[16];
    #pragma unroll
    for (int j = 0; j < 16; j++) acc[j] = 0.f;
    for (int mf0 = 0; mf0 < 127; mf0 += 16) {
        int nmf = (127 - mf0 < 16) ? (127 - mf0) : 16;
        __syncthreads();
        for (int i = tid; i < nmf*64; i += 512) {
            grs[i] = g_gr[(t*127 + mf0)*64 + i];
            gis[i] = g_gi[(t*127 + mf0)*64 + i];
        }
        for (int i = tid; i < nmf*128; i += 512) {
            cEs[i] = g_cE[mf0*128 + i];
            sEs[i] = g_sE[mf0*128 + i];
        }
        __syncthreads();
        for (int mm = 0; mm < nmf; mm++) {
            float gr = grs[mm*64 + o];
            float gi = gis[mm*64 + o];
            float4 c0 = *(const float4*)&cEs[mm*128 + kq*16 + 0];
            float4 c1 = *(const float4*)&cEs[mm*128 + kq*16 + 4];
            float4 c2 = *(const float4*)&cEs[mm*128 + kq*16 + 8];
            float4 c3 = *(const float4*)&cEs[mm*128 + kq*16 + 12];
            float4 s0 = *(const float4*)&sEs[mm*128 + kq*16 + 0];
            float4 s1 = *(const float4*)&sEs[mm*128 + kq*16 + 4];
            float4 s2 = *(const float4*)&sEs[mm*128 + kq*16 + 8];
            float4 s3 = *(const float4*)&sEs[mm*128 + kq*16 + 12];
            acc[0]  += gr*c0.x - gi*s0.x;
            acc[1]  += gr*c0.y - gi*s0.y;
            acc[2]  += gr*c0.z - gi*s0.z;
            acc[3]  += gr*c0.w - gi*s0.w;
            acc[4]  += gr*c1.x - gi*s1.x;
            acc[5]  += gr*c1.y - gi*s1.y;
            acc[6]  += gr*c1.z - gi*s1.z;
            acc[7]  += gr*c1.w - gi*s1.w;
            acc[8]  += gr*c2.x - gi*s2.x;
            acc[9]  += gr*c2.y - gi*s2.y;
            acc[10] += gr*c2.z - gi*s2.z;
            acc[11] += gr*c2.w - gi*s2.w;
            acc[12] += gr*c3.x - gi*s3.x;
            acc[13] += gr*c3.y - gi*s3.y;
            acc[14] += gr*c3.z - gi*s3.z;
            acc[15] += gr*c3.w - gi*s3.w;
        }
    }
    #pragma unroll
    for (int j = 0; j < 16; j++)
        g_xs[(t*128 + kq*16 + j)*64 + o] = acc[j];
}

// ---------------- fused conv path + add + LayerNorm + ReLU ---------------
__global__ void k_final(const float* __restrict__ x,
                        const float* __restrict__ ln_scale,
                        const float* __restrict__ ln_bias,
                        float* __restrict__ out) {
    int t = blockIdx.x;
    int w = threadIdx.x >> 5, lane = threadIdx.x & 31; // 8 warps
    float cw1 = g_cw[lane],       cw2 = g_cw[lane + 32];
    float tv1 = g_tv[lane],       tv2 = g_tv[lane + 32];
    float bt1 = g_bt[lane],       bt2 = g_bt[lane + 32];
    float lns1 = ln_scale[lane],  lnb1 = ln_bias[lane];
    float lns2 = ln_scale[lane+32], lnb2 = ln_bias[lane+32];
    float cb = g_cb[0];
    for (int k = w; k < 128; k += 8) {
        const float* xp = x + (t*128 + k)*64;
        float x1 = xp[lane], x2 = xp[lane + 32];
        float S = x1*cw1 + x2*cw2;
        #pragma unroll
        for (int off = 16; off; off >>= 1)
            S += __shfl_xor_sync(0xffffffffu, S, off);
        S += cb;
        const float* xsp = g_xs + (t*128 + k)*64;
        float v1 = xsp[lane]      + tv1*S + bt1;
        float v2 = xsp[lane + 32] + tv2*S + bt2;
        float s  = v1 + v2;
        float sq = v1*v1 + v2*v2;
        #pragma unroll
        for (int off = 16; off; off >>= 1) {
            s  += __shfl_xor_sync(0xffffffffu, s,  off);
            sq += __shfl_xor_sync(0xffffffffu, sq, off);
        }
        float mu   = s * (1.0f/64.0f);
        float var  = sq * (1.0f/64.0f) - mu*mu;
        float rstd = rsqrtf(var + 1e-6f);
        float r1 = (v1 - mu)*rstd*lns1 + lnb1;
        float r2 = (v2 - mu)*rstd*lns2 + lnb2;
        float* op = out + (t*128 + k)*64;
        op[lane]      = fmaxf(r1, 0.f);
        op[lane + 32] = fmaxf(r2, 0.f);
    }
}

// ---------------- launch -------------------------------------------------
extern "C" void kernel_launch(void* const* d_in, const int* in_sizes, int n_in,
                              void* d_out, int out_size) {
    const float* x        = (const float*)d_in[0];
    const float* t_emb    = (const float*)d_in[1];
    const float* wr       = (const float*)d_in[2];
    const float* wi       = (const float*)d_in[3];
    const float* conv_w   = (const float*)d_in[4];
    const float* conv_b   = (const float*)d_in[5];
    const float* time_w   = (const float*)d_in[6];
    const float* dense_w  = (const float*)d_in[7];
    const float* ln_scale = (const float*)d_in[8];
    const float* ln_bias  = (const float*)d_in[9];
    const float* P_in     = (const float*)d_in[10];
    const float* P_out    = (const float*)d_in[11];
    const float* quad_w   = (const float*)d_in[12];
    float* out = (float*)d_out;

    k_tab  <<<96, 256>>>();
    k_mod  <<<1, 128>>>(t_emb, dense_w, conv_w, conv_b, time_w);
    k_dft  <<<dim3(128, 4), 512>>>(x, quad_w);
    k_ana  <<<dim3(64, 4), 256>>>(P_in);
    k_wmul <<<dim3(127, 64), 256>>>(wr, wi);
    k_synl <<<127, 512>>>(P_out);
    k_ilon <<<128, 512>>>();
    k_final<<<128, 256>>>(x, ln_scale, ln_bias, out);
}

// round 7
// speedup vs baseline: 2.3985x; 1.4131x over previous
#include <cuda_runtime.h>
#include <math.h>

#define PI_F 3.14159265358979323846f

// ---- float4 helpers (nvcc contracts mul+add into FFMA) ----
__device__ __forceinline__ float4 operator+(float4 a, float4 b){ return make_float4(a.x+b.x,a.y+b.y,a.z+b.z,a.w+b.w); }
__device__ __forceinline__ float4 operator-(float4 a, float4 b){ return make_float4(a.x-b.x,a.y-b.y,a.z-b.z,a.w-b.w); }
__device__ __forceinline__ float4 operator*(float4 a, float s){ return make_float4(a.x*s,a.y*s,a.z*s,a.w*s); }
__device__ __forceinline__ void operator+=(float4& a, float4 b){ a.x+=b.x; a.y+=b.y; a.z+=b.z; a.w+=b.w; }
__device__ __forceinline__ void operator-=(float4& a, float4 b){ a.x-=b.x; a.y-=b.y; a.z-=b.z; a.w-=b.w; }

// ---------------- scratch ----------------
__device__ float g_Fr[64*128*64];    // [m][t][c]
__device__ float g_Fi[64*128*64];
__device__ float g_Fer[64*64*64];    // parity-folded F: [m][t<64][c]
__device__ float g_Fei[64*64*64];
__device__ float g_For[64*64*64];
__device__ float g_Foi[64*64*64];
__device__ float g_flmr[64*64*64];   // [l][m][c]
__device__ float g_flmi[64*64*64];
__device__ float g_glr[64*127*64];   // [l][mf][o]
__device__ float g_gli[64*127*64];
__device__ float g_gr[128*127*64];   // [t][mf][o]
__device__ float g_gi[128*127*64];
__device__ float g_xs[128*128*64];   // [t][k][o]
__device__ float g_cdftT[128*64];    // [n][m] cos
__device__ float g_sdftT[128*64];
__device__ float g_cE[127*128];      // [mf][k]
__device__ float g_sE[127*128];
__device__ float g_tv[64];
__device__ float g_bt[64];
__device__ float g_cw[64];
__device__ float g_cb[1];

// ---------------- twiddle tables ----------------
__global__ void k_tab() {
    int i = blockIdx.x * blockDim.x + threadIdx.x;
    const float w0 = 2.0f * PI_F / 128.0f;
    if (i < 128*64) {                       // transposed DFT table [n][m]
        int n = i >> 6, m = i & 63;
        int r = (m * n) & 127;
        float s, c; sincosf(w0 * (float)r, &s, &c);
        g_cdftT[i] = c; g_sdftT[i] = s;
    } else if (i < 128*64 + 127*128) {
        int j = i - 128*64;
        int mf = j >> 7, k = j & 127;
        int m = mf - 63;
        int r = ((m * k) % 128 + 128) & 127;
        float s, c; sincosf(w0 * (float)r, &s, &c);
        g_cE[mf*128 + k] = c; g_sE[mf*128 + k] = s;
    }
}

// ---------------- time-modulation precompute -----------------------------
__global__ void k_mod(const float* __restrict__ t_emb,
                      const float* __restrict__ dense_w,
                      const float* __restrict__ conv_w,
                      const float* __restrict__ conv_b,
                      const float* __restrict__ time_w) {
    __shared__ float psi[128];
    int tid = threadIdx.x;              // 128
    float s = 0.f;
    for (int d = 0; d < 256; d++) s += t_emb[d] * dense_w[d*128 + tid];
    psi[tid] = s;
    __syncthreads();
    if (tid < 64) {
        float tv = 0.f;
        for (int j = 0; j < 64; j++) tv += time_w[tid*64 + j] * psi[j];
        g_tv[tid] = tv;
        g_bt[tid] = psi[64 + tid];
        float cs = 0.f;
        for (int o = 0; o < 64; o++) cs += conv_w[tid*64 + o];
        g_cw[tid] = cs;
    }
    if (tid == 64) {
        float cb = 0.f;
        for (int o = 0; o < 64; o++) cb += conv_b[o];
        g_cb[0] = cb;
    }
}

// ---------------- longitude DFT with n-pairing (x real) ------------------
// Fr(m) = sum_{n=1..63} xe[n]c(mn) + x0 + (-1)^m x64
// Fi(m) = -sum_{n=1..63} xo[n]s(mn)
__global__ void k_dft(const float* __restrict__ x,
                      const float* __restrict__ quad_w) {
    int t = blockIdx.x;
    int tid = threadIdx.x;              // 512
    int cq = tid & 15, mg = tid >> 4;   // c = cq*4, m = mg*2+{0,1}
    __shared__ float xe[64*64], xo[64*64];   // [n][c]; row0 = x[0]/x[64]
    __shared__ float tc[32*64], tsn[32*64];  // chunk [n][m]
    const float4* xg = (const float4*)(x + t*8192);
    for (int i = tid; i < 1024; i += 512) {
        int n = i >> 4, f = i & 15;
        if (n == 0) {
            ((float4*)xe)[f] = xg[f];
            ((float4*)xo)[f] = xg[64*16 + f];
        } else {
            float4 a = xg[n*16 + f];
            float4 b = xg[(128 - n)*16 + f];
            ((float4*)xe)[i] = a + b;
            ((float4*)xo)[i] = a - b;
        }
    }
    float4 a0r = {0,0,0,0}, a0i = {0,0,0,0}, a1r = {0,0,0,0}, a1i = {0,0,0,0};
    for (int ch = 0; ch < 2; ch++) {
        __syncthreads();
        for (int i = tid; i < 512; i += 512) {
            ((float4*)tc)[i]  = ((const float4*)g_cdftT)[ch*512 + i];
            ((float4*)tsn)[i] = ((const float4*)g_sdftT)[ch*512 + i];
        }
        __syncthreads();
        int nstart = ch ? 0 : 1;
        #pragma unroll 4
        for (int ln = nstart; ln < 32; ln++) {
            float4 xev = ((float4*)xe)[(ch*32 + ln)*16 + cq];
            float4 xov = ((float4*)xo)[(ch*32 + ln)*16 + cq];
            float2 cv = ((float2*)tc)[ln*32 + mg];
            float2 sv = ((float2*)tsn)[ln*32 + mg];
            a0r += xev * cv.x;  a0i -= xov * sv.x;
            a1r += xev * cv.y;  a1i -= xov * sv.y;
        }
    }
    float4 x0  = ((float4*)xe)[cq];
    float4 x64 = ((float4*)xo)[cq];
    a0r += x0 + x64;        // m even
    a1r += x0 - x64;        // m odd
    float scale = (2.0f * PI_F / 128.0f) * quad_w[t];
    int m = mg*2;
    *(float4*)(g_Fr + (m*128 + t)*64 + cq*4)     = a0r * scale;
    *(float4*)(g_Fi + (m*128 + t)*64 + cq*4)     = a0i * scale;
    *(float4*)(g_Fr + ((m+1)*128 + t)*64 + cq*4) = a1r * scale;
    *(float4*)(g_Fi + ((m+1)*128 + t)*64 + cq*4) = a1i * scale;
}

// ---------------- parity fold of F over theta ----------------------------
__global__ void k_par() {
    int i = blockIdx.x * 256 + threadIdx.x;  // 65536
    int m = i >> 10, t = (i >> 4) & 63, f = i & 15;
    const float4* Fr4 = (const float4*)g_Fr;
    const float4* Fi4 = (const float4*)g_Fi;
    float4 a = Fr4[(m*128 + t)*16 + f];
    float4 b = Fr4[(m*128 + 127 - t)*16 + f];
    ((float4*)g_Fer)[(m*64 + t)*16 + f] = a + b;
    ((float4*)g_For)[(m*64 + t)*16 + f] = a - b;
    a = Fi4[(m*128 + t)*16 + f];
    b = Fi4[(m*128 + 127 - t)*16 + f];
    ((float4*)g_Fei)[(m*64 + t)*16 + f] = a + b;
    ((float4*)g_Foi)[(m*64 + t)*16 + f] = a - b;
}

// ---------------- Legendre analysis (parity-halved) ----------------------
__global__ void k_ana(const float* __restrict__ P_in) {
    int m = blockIdx.x, l0 = blockIdx.y * 16;
    int tid = threadIdx.x;              // 256
    int cq = tid & 15, li = tid >> 4;
    int l = l0 + li;
    __shared__ float Ps[16*64];         // [li][t<64]
    for (int i = tid; i < 16*16; i += 256)
        ((float4*)Ps)[i] = *(const float4*)(P_in + (size_t)((l0 + (i >> 4))*127 + 63 + m)*128 + (i & 15)*4);
    __syncthreads();
    int p = (l + m) & 1;
    const float4* Fr4 = (const float4*)((p ? g_For : g_Fer) + m*4096);
    const float4* Fi4 = (const float4*)((p ? g_Foi : g_Fei) + m*4096);
    float4 ar = {0,0,0,0}, ai = {0,0,0,0};
    #pragma unroll 4
    for (int tt = 0; tt < 64; tt++) {
        float pv = Ps[li*64 + tt];
        float4 fr = Fr4[tt*16 + cq];
        float4 fi = Fi4[tt*16 + cq];
        ar += fr * pv;
        ai += fi * pv;
    }
    *(float4*)(g_flmr + (l*64 + m)*64 + cq*4) = ar;
    *(float4*)(g_flmi + (l*64 + m)*64 + cq*4) = ai;
}

// ---------------- complex spectral weight multiply (266 MB stream) -------
__global__ void k_wmul(const float* __restrict__ wr,
                       const float* __restrict__ wi) {
    int mf = blockIdx.x, l = blockIdx.y;
    int tid = threadIdx.x;              // 256
    int og = tid & 15;
    int ig = tid >> 4;
    __shared__ float ar[64], ai[64];
    __shared__ float redr[16][64], redi[16][64];
    if (tid < 64) {
        int i = tid;
        float r, im;
        if (mf >= 63) {
            int m = mf - 63;
            r  = g_flmr[(l*64 + m)*64 + i];
            im = g_flmi[(l*64 + m)*64 + i];
        } else {
            int m = 63 - mf;
            float sgn = (m & 1) ? -1.f : 1.f;
            r  =  sgn * g_flmr[(l*64 + m)*64 + i];
            im = -sgn * g_flmi[(l*64 + m)*64 + i];
        }
        ar[i] = r; ai[i] = im;
    }
    __syncthreads();
    const float4* wr4 = (const float4*)(wr + (size_t)(l*127 + mf)*4096);
    const float4* wi4 = (const float4*)(wi + (size_t)(l*127 + mf)*4096);
    float4 gr = {0,0,0,0}, gi = {0,0,0,0};
    #pragma unroll
    for (int ii = 0; ii < 4; ii++) {
        int i = ig*4 + ii;
        float4 wrv = wr4[i*16 + og];
        float4 wiv = wi4[i*16 + og];
        float xr = ar[i], xi = ai[i];
        gr.x += xr*wrv.x - xi*wiv.x;  gi.x += xr*wiv.x + xi*wrv.x;
        gr.y += xr*wrv.y - xi*wiv.y;  gi.y += xr*wiv.y + xi*wrv.y;
        gr.z += xr*wrv.z - xi*wiv.z;  gi.z += xr*wiv.z + xi*wrv.z;
        gr.w += xr*wrv.w - xi*wiv.w;  gi.w += xr*wiv.w + xi*wrv.w;
    }
    *(float4*)&redr[ig][og*4] = gr;
    *(float4*)&redi[ig][og*4] = gi;
    __syncthreads();
    if (tid < 64) {
        float sr = 0.f, si = 0.f;
        #pragma unroll
        for (int g = 0; g < 16; g++) { sr += redr[g][tid]; si += redi[g][tid]; }
        g_glr[(l*127 + mf)*64 + tid] = sr;
        g_gli[(l*127 + mf)*64 + tid] = si;
    }
}

// ---------------- Legendre synthesis (theta-parity folded) ---------------
// A = sum over l with (l+m) even, B = odd. g[t] = A+B; g[127-t] = A-B.
__global__ void k_synl(const float* __restrict__ P_out) {
    int mf = blockIdx.x;
    int m = (mf >= 63) ? (mf - 63) : (63 - mf);
    int tid = threadIdx.x;              // 256
    int og = tid & 15, tg = tid >> 4;   // t = tg*4+j, t < 64
    __shared__ float glsr[64*64], glsi[64*64];  // [l][o]
    __shared__ float Ps[64*64];                 // [l][t<64]
    for (int i = tid; i < 64*16; i += 256) {
        int l = i >> 4, f = i & 15;
        ((float4*)glsr)[i] = *(const float4*)(g_glr + (l*127 + mf)*64 + f*4);
        ((float4*)glsi)[i] = *(const float4*)(g_gli + (l*127 + mf)*64 + f*4);
        ((float4*)Ps)[i]   = *(const float4*)(P_out + (size_t)(l*127 + mf)*128 + f*4);
    }
    __syncthreads();
    float4 Ar[4], Ai[4], Br[4], Bi[4];
    #pragma unroll
    for (int j = 0; j < 4; j++) {
        Ar[j] = make_float4(0,0,0,0); Ai[j] = make_float4(0,0,0,0);
        Br[j] = make_float4(0,0,0,0); Bi[j] = make_float4(0,0,0,0);
    }
    int pA = m & 1;
    #pragma unroll 2
    for (int j2 = 0; j2 < 32; j2++) {
        int lA = pA + 2*j2, lB = (pA ^ 1) + 2*j2;
        float4 grA = ((float4*)glsr)[lA*16 + og];
        float4 giA = ((float4*)glsi)[lA*16 + og];
        float4 pAv = ((float4*)Ps)[lA*16 + tg];
        float4 grB = ((float4*)glsr)[lB*16 + og];
        float4 giB = ((float4*)glsi)[lB*16 + og];
        float4 pBv = ((float4*)Ps)[lB*16 + tg];
        Ar[0] += grA * pAv.x;  Ai[0] += giA * pAv.x;
        Ar[1] += grA * pAv.y;  Ai[1] += giA * pAv.y;
        Ar[2] += grA * pAv.z;  Ai[2] += giA * pAv.z;
        Ar[3] += grA * pAv.w;  Ai[3] += giA * pAv.w;
        Br[0] += grB * pBv.x;  Bi[0] += giB * pBv.x;
        Br[1] += grB * pBv.y;  Bi[1] += giB * pBv.y;
        Br[2] += grB * pBv.z;  Bi[2] += giB * pBv.z;
        Br[3] += grB * pBv.w;  Bi[3] += giB * pBv.w;
    }
    #pragma unroll
    for (int j = 0; j < 4; j++) {
        int t  = tg*4 + j;
        int t2 = 127 - t;
        *(float4*)(g_gr + (t *127 + mf)*64 + og*4) = Ar[j] + Br[j];
        *(float4*)(g_gi + (t *127 + mf)*64 + og*4) = Ai[j] + Bi[j];
        *(float4*)(g_gr + (t2*127 + mf)*64 + og*4) = Ar[j] - Br[j];
        *(float4*)(g_gi + (t2*127 + mf)*64 + og*4) = Ai[j] - Bi[j];
    }
}

// ---------------- inverse longitude (m-fold + k-fold) --------------------
// Gr[mm]=gr(63+mm)+gr(63-mm), Gi[mm]=gi(63+mm)-gi(63-mm) (mm=0: just gr/gi at 63)
// A(k)=sum Gr*c, B(k)=sum Gi*s over mm=0..63 (rows 63+mm of cE/sE)
// x[k]=A-B (k<=64); x[128-k]=A+B (1<=k<=63)
__global__ void k_ilon() {
    int t = blockIdx.x;
    int tid = threadIdx.x;              // 320
    int og = tid & 15, kg = tid >> 4;   // kg 0..19; k' = kg*4+j
    bool act = (kg <= 16);
    __shared__ float GrS[16*64], GiS[16*64];
    __shared__ float cS[16*68], sS[16*68];
    float4 A[4], B[4];
    #pragma unroll
    for (int j = 0; j < 4; j++) { A[j] = make_float4(0,0,0,0); B[j] = make_float4(0,0,0,0); }
    for (int ch = 0; ch < 4; ch++) {
        int mm0 = ch * 16;
        __syncthreads();
        for (int i = tid; i < 16*16; i += 320) {
            int mm = i >> 4, f = i & 15;
            int MM = mm0 + mm;
            float4 grv = *((const float4*)(g_gr + (t*127 + 63 + MM)*64) + f);
            float4 giv = *((const float4*)(g_gi + (t*127 + 63 + MM)*64) + f);
            if (MM) {
                grv += *((const float4*)(g_gr + (t*127 + 63 - MM)*64) + f);
                giv -= *((const float4*)(g_gi + (t*127 + 63 - MM)*64) + f);
            }
            ((float4*)GrS)[i] = grv;
            ((float4*)GiS)[i] = giv;
        }
        for (int i = tid; i < 16*17; i += 320) {
            int mm = i / 17, f = i % 17;
            ((float4*)cS)[i] = *(const float4*)(g_cE + (63 + mm0 + mm)*128 + f*4);
            ((float4*)sS)[i] = *(const float4*)(g_sE + (63 + mm0 + mm)*128 + f*4);
        }
        __syncthreads();
        if (act) {
            #pragma unroll 4
            for (int mm = 0; mm < 16; mm++) {
                float4 Gr = ((float4*)GrS)[mm*16 + og];
                float4 Gi = ((float4*)GiS)[mm*16 + og];
                float4 cv = *(float4*)&cS[mm*68 + kg*4];
                float4 sv = *(float4*)&sS[mm*68 + kg*4];
                A[0] += Gr * cv.x;  B[0] += Gi * sv.x;
                A[1] += Gr * cv.y;  B[1] += Gi * sv.y;
                A[2] += Gr * cv.z;  B[2] += Gi * sv.z;
                A[3] += Gr * cv.w;  B[3] += Gi * sv.w;
            }
        }
    }
    if (act) {
        #pragma unroll
        for (int j = 0; j < 4; j++) {
            int k = kg*4 + j;
            if (k <= 64) {
                *(float4*)(g_xs + (t*128 + k)*64 + og*4) = A[j] - B[j];
                if (k >= 1 && k <= 63)
                    *(float4*)(g_xs + (t*128 + 128 - k)*64 + og*4) = A[j] + B[j];
            }
        }
    }
}

// ---------------- fused conv path + add + LayerNorm + ReLU ---------------
__global__ void k_final(const float* __restrict__ x,
                        const float* __restrict__ ln_scale,
                        const float* __restrict__ ln_bias,
                        float* __restrict__ out) {
    int t = blockIdx.x;
    int w = threadIdx.x >> 5, lane = threadIdx.x & 31; // 8 warps
    float cw1 = g_cw[lane],       cw2 = g_cw[lane + 32];
    float tv1 = g_tv[lane],       tv2 = g_tv[lane + 32];
    float bt1 = g_bt[lane],       bt2 = g_bt[lane + 32];
    float lns1 = ln_scale[lane],  lnb1 = ln_bias[lane];
    float lns2 = ln_scale[lane+32], lnb2 = ln_bias[lane+32];
    float cb = g_cb[0];
    for (int k = w; k < 128; k += 8) {
        const float* xp = x + (t*128 + k)*64;
        float x1 = xp[lane], x2 = xp[lane + 32];
        float S = x1*cw1 + x2*cw2;
        #pragma unroll
        for (int off = 16; off; off >>= 1)
            S += __shfl_xor_sync(0xffffffffu, S, off);
        S += cb;
        const float* xsp = g_xs + (t*128 + k)*64;
        float v1 = xsp[lane]      + tv1*S + bt1;
        float v2 = xsp[lane + 32] + tv2*S + bt2;
        float s  = v1 + v2;
        float sq = v1*v1 + v2*v2;
        #pragma unroll
        for (int off = 16; off; off >>= 1) {
            s  += __shfl_xor_sync(0xffffffffu, s,  off);
            sq += __shfl_xor_sync(0xffffffffu, sq, off);
        }
        float mu   = s * (1.0f/64.0f);
        float var  = sq * (1.0f/64.0f) - mu*mu;
        float rstd = rsqrtf(var + 1e-6f);
        float r1 = (v1 - mu)*rstd*lns1 + lnb1;
        float r2 = (v2 - mu)*rstd*lns2 + lnb2;
        float* op = out + (t*128 + k)*64;
        op[lane]      = fmaxf(r1, 0.f);
        op[lane + 32] = fmaxf(r2, 0.f);
    }
}

// ---------------- launch -------------------------------------------------
extern "C" void kernel_launch(void* const* d_in, const int* in_sizes, int n_in,
                              void* d_out, int out_size) {
    const float* x        = (const float*)d_in[0];
    const float* t_emb    = (const float*)d_in[1];
    const float* wr       = (const float*)d_in[2];
    const float* wi       = (const float*)d_in[3];
    const float* conv_w   = (const float*)d_in[4];
    const float* conv_b   = (const float*)d_in[5];
    const float* time_w   = (const float*)d_in[6];
    const float* dense_w  = (const float*)d_in[7];
    const float* ln_scale = (const float*)d_in[8];
    const float* ln_bias  = (const float*)d_in[9];
    const float* P_in     = (const float*)d_in[10];
    const float* P_out    = (const float*)d_in[11];
    const float* quad_w   = (const float*)d_in[12];
    float* out = (float*)d_out;

    k_tab  <<<96, 256>>>();
    k_mod  <<<1, 128>>>(t_emb, dense_w, conv_w, conv_b, time_w);
    k_dft  <<<128, 512>>>(x, quad_w);
    k_par  <<<256, 256>>>();
    k_ana  <<<dim3(64, 4), 256>>>(P_in);
    k_wmul <<<dim3(127, 64), 256>>>(wr, wi);
    k_synl <<<127, 256>>>(P_out);
    k_ilon <<<128, 320>>>();
    k_final<<<128, 256>>>(x, ln_scale, ln_bias, out);
}